// round 4
// baseline (speedup 1.0000x reference)
#include <cuda_runtime.h>
#include <cuda_bf16.h>
#include <cstdint>

#define MAX_N 50000
#define MAX_E 800000
#define HDIM  64

// ---------------- scratch (no allocations allowed) ----------------
__device__ float g_tx[2L * MAX_N * HDIM];   // [2][N][64] per-relation transforms
__device__ float g_bufA[MAX_N * HDIM];
__device__ float g_bufB[MAX_N * HDIM];
__device__ float g_ev[2L * MAX_N * 2];      // [2][N][2] layer-3 messages
__device__ int   g_cnt[MAX_N];
__device__ int   g_off[MAX_N + 1];
__device__ int   g_pos[MAX_N];
__device__ unsigned g_elist[MAX_E];         // packed: src | (etype<<16)   (src < 65536)
__device__ unsigned g_min_key;
// pre-split bf16 weights: [3][K][64] hi/lo per layer
__device__ __nv_bfloat16 g_w1h[3 * 128 * 64], g_w1l[3 * 128 * 64];
__device__ __nv_bfloat16 g_w2h[3 * 64 * 64],  g_w2l[3 * 64 * 64];

// monotone float<->uint encoding so atomicMin(uint) == float min
__device__ __forceinline__ unsigned fenc(float f) {
    unsigned b = __float_as_uint(f);
    return (b & 0x80000000u) ? ~b : (b | 0x80000000u);
}
__device__ __forceinline__ float fdec(unsigned k) {
    unsigned b = (k & 0x80000000u) ? (k ^ 0x80000000u) : ~k;
    return __uint_as_float(b);
}
__device__ __forceinline__ void split_bf16(float v, __nv_bfloat16& h, __nv_bfloat16& l) {
    h = __float2bfloat16(v);
    l = __float2bfloat16(v - __bfloat162float(h));
}

// ================= weight pre-split (runs once per launch, tiny) =================
__global__ void presplit_kernel(const float* __restrict__ W1, const float* __restrict__ L1,
                                const float* __restrict__ W2, const float* __restrict__ L2)
{
    int i = blockIdx.x * blockDim.x + threadIdx.x;
    if (i < 24576) {            // layer 1: [2][128][64] + [128][64]
        float v = (i < 16384) ? W1[i] : L1[i - 16384];
        split_bf16(v, g_w1h[i], g_w1l[i]);
    } else if (i < 24576 + 12288) {  // layer 2: [2][64][64] + [64][64]
        int j = i - 24576;
        float v = (j < 8192) ? W2[j] : L2[j - 8192];
        split_bf16(v, g_w2h[j], g_w2l[j]);
    }
}

// ================= CSR build =================
__global__ void zero_cnt_kernel(int N) {
    int i = blockIdx.x * blockDim.x + threadIdx.x;
    if (i < N) g_cnt[i] = 0;
    if (i == 0) g_min_key = 0xFFFFFFFFu;
}

__global__ void hist_kernel(const int* __restrict__ dst, int E) {
    int e = blockIdx.x * blockDim.x + threadIdx.x;
    if (e < E) atomicAdd(&g_cnt[dst[e]], 1);
}

// single-block chunked exclusive scan (proven in R2)
__global__ void __launch_bounds__(1024) scan_kernel(int N) {
    __shared__ int sa[1024], sb[1024];
    const int tid = threadIdx.x;
    const int chunk = (N + 1023) / 1024;
    const int base = tid * chunk;
    const int lim = min(base + chunk, N);

    int s0 = 0, s1 = 0, s2 = 0, s3 = 0;
    int i = base;
    for (; i + 4 <= lim; i += 4) {
        s0 += g_cnt[i]; s1 += g_cnt[i + 1]; s2 += g_cnt[i + 2]; s3 += g_cnt[i + 3];
    }
    for (; i < lim; i++) s0 += g_cnt[i];
    int sum = s0 + s1 + s2 + s3;

    sa[tid] = sum;
    __syncthreads();
    int* in = sa; int* out = sb;
    #pragma unroll
    for (int o = 1; o < 1024; o <<= 1) {
        out[tid] = in[tid] + (tid >= o ? in[tid - o] : 0);
        __syncthreads();
        int* t = in; in = out; out = t;
    }
    int run = in[tid] - sum;
    for (int k = base; k < lim; k++) {
        g_off[k] = run; g_pos[k] = run;
        run += g_cnt[k];
    }
    if (tid == 1023) g_off[N] = in[1023];
}

__global__ void fill_kernel(const int* __restrict__ src,
                            const int* __restrict__ dst,
                            const int* __restrict__ et, int E) {
    int e = blockIdx.x * blockDim.x + threadIdx.x;
    if (e >= E) return;
    int p = atomicAdd(&g_pos[dst[e]], 1);
    g_elist[p] = (unsigned)src[e] | ((unsigned)et[e] << 16);
}

// ================= tensor-core helpers =================
__device__ __forceinline__ void ldsm_x4(uint32_t* r, const void* p) {
    uint32_t a = (uint32_t)__cvta_generic_to_shared(p);
    asm volatile("ldmatrix.sync.aligned.m8n8.x4.shared.b16 {%0,%1,%2,%3}, [%4];"
        : "=r"(r[0]), "=r"(r[1]), "=r"(r[2]), "=r"(r[3]) : "r"(a));
}
__device__ __forceinline__ void ldsm_x2t(uint32_t* r, const void* p) {
    uint32_t a = (uint32_t)__cvta_generic_to_shared(p);
    asm volatile("ldmatrix.sync.aligned.m8n8.x2.trans.shared.b16 {%0,%1}, [%2];"
        : "=r"(r[0]), "=r"(r[1]) : "r"(a));
}
__device__ __forceinline__ void mma_bf16(float* c, const uint32_t* a, const uint32_t* b) {
    asm volatile("mma.sync.aligned.m16n8k16.row.col.f32.bf16.bf16.f32 "
        "{%0,%1,%2,%3}, {%4,%5,%6,%7}, {%8,%9}, {%0,%1,%2,%3};"
        : "+f"(c[0]), "+f"(c[1]), "+f"(c[2]), "+f"(c[3])
        : "r"(a[0]), "r"(a[1]), "r"(a[2]), "r"(a[3]), "r"(b[0]), "r"(b[1]));
}

// ================= tensor-core triple GEMM v2 =================
// {C0,C1,Cl} = relu?(A[M,K]) @ bf16split(W[3][K][64]) (+bias on Cl). BM=128.
template<int K, bool RELU_IN>
__global__ void __launch_bounds__(256, 1) gemm_tc2_kernel(
    const float* __restrict__ A, int M,
    const __nv_bfloat16* __restrict__ Wh, const __nv_bfloat16* __restrict__ Wl,
    const float* __restrict__ bias,
    float* __restrict__ C0, float* __restrict__ C1, float* __restrict__ Cl)
{
    constexpr int BM = 128;
    constexpr int AS = K + 8;
    constexpr int WS = 72;
    extern __shared__ __nv_bfloat16 sm[];
    __nv_bfloat16* Ahi = sm;                    // [BM][AS]
    __nv_bfloat16* Alo = Ahi + BM * AS;
    __nv_bfloat16* Whs = Alo + BM * AS;         // [3][K][WS]
    __nv_bfloat16* Wls = Whs + 3 * K * WS;

    const int tid  = threadIdx.x;
    const int lane = tid & 31;
    const int warp = tid >> 5;
    const int rowBase = blockIdx.x * BM;

    // ---- copy pre-split weights (bf16, vectorized) ----
    for (int u = tid; u < 3 * K * 8; u += 256) {
        int row = u >> 3, col = (u & 7) * 8;
        *(uint4*)&Whs[row * WS + col] = *(const uint4*)&Wh[row * 64 + col];
        *(uint4*)&Wls[row * WS + col] = *(const uint4*)&Wl[row * 64 + col];
    }
    // ---- load & split A tile ----
    for (int i = tid * 4; i < BM * K; i += 1024) {
        int r = i / K, kq = i % K;
        float4 v = make_float4(0.f, 0.f, 0.f, 0.f);
        if (rowBase + r < M) v = *(const float4*)&A[(long)(rowBase + r) * K + kq];
        float vv[4] = {v.x, v.y, v.z, v.w};
        #pragma unroll
        for (int j = 0; j < 4; j++) {
            float x = RELU_IN ? fmaxf(vv[j], 0.f) : vv[j];
            __nv_bfloat16 h, l;
            split_bf16(x, h, l);
            Ahi[r * AS + kq + j] = h;
            Alo[r * AS + kq + j] = l;
        }
    }
    __syncthreads();

    // 4 warps in M (32 rows each = 2 m16 tiles), 2 warps in N (96 cols each)
    const int mw = (warp & 3) * 32;
    const int nw = (warp >> 2) * 96;
    const int lr = lane & 15;
    const int aCol = (lane >> 4) * 8;

    float acc[2][12][4];
    #pragma unroll
    for (int mt = 0; mt < 2; mt++)
        #pragma unroll
        for (int j = 0; j < 12; j++)
            #pragma unroll
            for (int q = 0; q < 4; q++) acc[mt][j][q] = 0.f;

    #pragma unroll
    for (int kk = 0; kk < K / 16; kk++) {
        uint32_t ah[2][4], al[2][4];
        #pragma unroll
        for (int mt = 0; mt < 2; mt++) {
            ldsm_x4(ah[mt], &Ahi[(mw + mt * 16 + lr) * AS + kk * 16 + aCol]);
            ldsm_x4(al[mt], &Alo[(mw + mt * 16 + lr) * AS + kk * 16 + aCol]);
        }
        #pragma unroll
        for (int j = 0; j < 12; j++) {
            int n = nw + j * 8;
            int w = n >> 6, nc = n & 63;
            long woff = (long)(w * K + kk * 16 + lr) * WS + nc;
            uint32_t bh[2], bl[2];
            ldsm_x2t(bh, &Whs[woff]);
            ldsm_x2t(bl, &Wls[woff]);
            mma_bf16(acc[0][j], ah[0], bh);
            mma_bf16(acc[0][j], ah[0], bl);
            mma_bf16(acc[0][j], al[0], bh);
            mma_bf16(acc[1][j], ah[1], bh);
            mma_bf16(acc[1][j], ah[1], bl);
            mma_bf16(acc[1][j], al[1], bh);
        }
    }

    // ---- epilogue ----
    float* Cs[3] = {C0, C1, Cl};
    #pragma unroll
    for (int mt = 0; mt < 2; mt++) {
        const int r0 = rowBase + mw + mt * 16 + (lane >> 2);
        #pragma unroll
        for (int j = 0; j < 12; j++) {
            int n = nw + j * 8;
            int w = n >> 6;
            int nc = (n & 63) + 2 * (lane & 3);
            float b0 = 0.f, b1 = 0.f;
            if (w == 2) { b0 = bias[nc]; b1 = bias[nc + 1]; }
            if (r0 < M)
                *(float2*)&Cs[w][(long)r0 * 64 + nc] =
                    make_float2(acc[mt][j][0] + b0, acc[mt][j][1] + b1);
            if (r0 + 8 < M)
                *(float2*)&Cs[w][(long)(r0 + 8) * 64 + nc] =
                    make_float2(acc[mt][j][2] + b0, acc[mt][j][3] + b1);
        }
    }
}

// ================= gather aggregation (CSR, MLP=4, no atomics) =================
__global__ void gather64_kernel(const float* __restrict__ t,
                                float* __restrict__ agg, int N)
{
    int w = (int)((blockIdx.x * (long)blockDim.x + threadIdx.x) >> 5);
    int lane = threadIdx.x & 31;
    if (w >= N) return;
    int beg = g_off[w], end = g_off[w + 1];
    long o = (long)w * 64 + lane * 2;
    float2 a0 = *(float2*)&agg[o];          // self-loop + bias already there
    float2 a1 = make_float2(0.f, 0.f), a2 = a1, a3 = a1;
    int e = beg;
    for (; e + 4 <= end; e += 4) {
        unsigned p0 = g_elist[e],     p1 = g_elist[e + 1];
        unsigned p2 = g_elist[e + 2], p3 = g_elist[e + 3];
        float2 v0 = *(const float2*)&t[(long)((p0 >> 16) * N + (p0 & 0xFFFFu)) * 64 + lane * 2];
        float2 v1 = *(const float2*)&t[(long)((p1 >> 16) * N + (p1 & 0xFFFFu)) * 64 + lane * 2];
        float2 v2 = *(const float2*)&t[(long)((p2 >> 16) * N + (p2 & 0xFFFFu)) * 64 + lane * 2];
        float2 v3 = *(const float2*)&t[(long)((p3 >> 16) * N + (p3 & 0xFFFFu)) * 64 + lane * 2];
        a0.x += v0.x; a0.y += v0.y;
        a1.x += v1.x; a1.y += v1.y;
        a2.x += v2.x; a2.y += v2.y;
        a3.x += v3.x; a3.y += v3.y;
    }
    for (; e < end; e++) {
        unsigned p = g_elist[e];
        float2 v = *(const float2*)&t[(long)((p >> 16) * N + (p & 0xFFFFu)) * 64 + lane * 2];
        a0.x += v.x; a0.y += v.y;
    }
    a0.x += a1.x + a2.x + a3.x;
    a0.y += a1.y + a2.y + a3.y;
    *(float2*)&agg[o] = a0;
}

__global__ void gather2_kernel(const float* __restrict__ ev,
                               float* __restrict__ out, int N)
{
    int n = blockIdx.x * blockDim.x + threadIdx.x;
    if (n >= N) return;
    int beg = g_off[n], end = g_off[n + 1];
    float2 a0 = *(float2*)&out[n * 2];
    float2 a1 = make_float2(0.f, 0.f), a2 = a1, a3 = a1;
    int e = beg;
    for (; e + 4 <= end; e += 4) {
        unsigned p0 = g_elist[e],     p1 = g_elist[e + 1];
        unsigned p2 = g_elist[e + 2], p3 = g_elist[e + 3];
        float2 v0 = *(const float2*)&ev[(long)((p0 >> 16) * N + (p0 & 0xFFFFu)) * 2];
        float2 v1 = *(const float2*)&ev[(long)((p1 >> 16) * N + (p1 & 0xFFFFu)) * 2];
        float2 v2 = *(const float2*)&ev[(long)((p2 >> 16) * N + (p2 & 0xFFFFu)) * 2];
        float2 v3 = *(const float2*)&ev[(long)((p3 >> 16) * N + (p3 & 0xFFFFu)) * 2];
        a0.x += v0.x; a0.y += v0.y;
        a1.x += v1.x; a1.y += v1.y;
        a2.x += v2.x; a2.y += v2.y;
        a3.x += v3.x; a3.y += v3.y;
    }
    for (; e < end; e++) {
        unsigned p = g_elist[e];
        float2 v = *(const float2*)&ev[(long)((p >> 16) * N + (p & 0xFFFFu)) * 2];
        a0.x += v.x; a0.y += v.y;
    }
    a0.x += a1.x + a2.x + a3.x;
    a0.y += a1.y + a2.y + a3.y;
    *(float2*)&out[n * 2] = a0;
}

// ================= layer 3 per-node transforms =================
__global__ void layer3_kernel(
    const float* __restrict__ H,
    const float* __restrict__ W3, const float* __restrict__ L3,
    const float* __restrict__ b3,
    float* __restrict__ ev, float* __restrict__ out, int N)
{
    __shared__ float sW0[128], sW1[128], sL[128], sb[2];
    int tid = threadIdx.x;
    for (int i = tid; i < 128; i += blockDim.x) {
        sW0[i] = W3[i];
        sW1[i] = W3[128 + i];
        sL[i]  = L3[i];
    }
    if (tid < 2) sb[tid] = b3[tid];
    __syncthreads();

    int n = blockIdx.x * blockDim.x + tid;
    if (n >= N) return;
    const float* h = &H[(long)n * 64];
    float a0 = 0.f, a1 = 0.f, c0 = 0.f, c1 = 0.f, l0 = 0.f, l1 = 0.f;
    #pragma unroll
    for (int k = 0; k < 64; k += 4) {
        float4 hv = *(const float4*)&h[k];
        float xv[4] = {fmaxf(hv.x, 0.f), fmaxf(hv.y, 0.f),
                       fmaxf(hv.z, 0.f), fmaxf(hv.w, 0.f)};
        #pragma unroll
        for (int j = 0; j < 4; j++) {
            int kk = k + j;
            a0 = fmaf(xv[j], sW0[kk * 2 + 0], a0);
            a1 = fmaf(xv[j], sW0[kk * 2 + 1], a1);
            c0 = fmaf(xv[j], sW1[kk * 2 + 0], c0);
            c1 = fmaf(xv[j], sW1[kk * 2 + 1], c1);
            l0 = fmaf(xv[j], sL[kk * 2 + 0], l0);
            l1 = fmaf(xv[j], sL[kk * 2 + 1], l1);
        }
    }
    *(float2*)&ev[n * 2] = make_float2(a0, a1);
    *(float2*)&ev[((long)N + n) * 2] = make_float2(c0, c1);
    *(float2*)&out[n * 2] = make_float2(l0 + sb[0], l1 + sb[1]);
}

// ================= global min + mask =================
__global__ void min_kernel(const float* __restrict__ v, int n)
{
    float m = 3.402823466e+38f;
    for (int i = blockIdx.x * blockDim.x + threadIdx.x; i < n;
         i += gridDim.x * blockDim.x)
        m = fminf(m, v[i]);
    #pragma unroll
    for (int o = 16; o; o >>= 1)
        m = fminf(m, __shfl_xor_sync(0xffffffffu, m, o));
    __shared__ float sm[8];
    if ((threadIdx.x & 31) == 0) sm[threadIdx.x >> 5] = m;
    __syncthreads();
    if (threadIdx.x < 8) {
        m = sm[threadIdx.x];
        #pragma unroll
        for (int o = 4; o; o >>= 1)
            m = fminf(m, __shfl_xor_sync(0xffu, m, o));
        if (threadIdx.x == 0) atomicMin(&g_min_key, fenc(m));
    }
}

__global__ void mask_kernel(float* __restrict__ out,
                            const int* __restrict__ cs,
                            const int* __restrict__ ms, int N)
{
    int n = blockIdx.x * blockDim.x + threadIdx.x;
    if (n >= N) return;
    float mn = fdec(g_min_key) - 1.0f;
    float2 v = *(float2*)&out[n * 2];
    if (cs[n] >= ms[n] - 1) v.x = mn;
    if (cs[n] == 0)         v.y = mn;
    *(float2*)&out[n * 2] = v;
}

// ================= launch =================
extern "C" void kernel_launch(void* const* d_in, const int* in_sizes, int n_in,
                              void* d_out, int out_size)
{
    const float* x  = (const float*)d_in[0];
    const int* src  = (const int*)d_in[1];
    const int* dst  = (const int*)d_in[2];
    const int* et   = (const int*)d_in[3];
    const int* cs   = (const int*)d_in[4];
    const int* ms   = (const int*)d_in[5];
    const float* W1 = (const float*)d_in[6];
    const float* L1 = (const float*)d_in[7];
    const float* b1 = (const float*)d_in[8];
    const float* W2 = (const float*)d_in[9];
    const float* L2 = (const float*)d_in[10];
    const float* b2 = (const float*)d_in[11];
    const float* W3 = (const float*)d_in[12];
    const float* L3 = (const float*)d_in[13];
    const float* b3 = (const float*)d_in[14];

    const int N = in_sizes[0] / 128;
    const int E = in_sizes[1];
    float* out = (float*)d_out;

    float *tx, *bufA, *bufB, *ev;
    __nv_bfloat16 *w1h, *w1l, *w2h, *w2l;
    cudaGetSymbolAddress((void**)&tx,   g_tx);
    cudaGetSymbolAddress((void**)&bufA, g_bufA);
    cudaGetSymbolAddress((void**)&bufB, g_bufB);
    cudaGetSymbolAddress((void**)&ev,   g_ev);
    cudaGetSymbolAddress((void**)&w1h,  g_w1h);
    cudaGetSymbolAddress((void**)&w1l,  g_w1l);
    cudaGetSymbolAddress((void**)&w2h,  g_w2h);
    cudaGetSymbolAddress((void**)&w2l,  g_w2l);

    constexpr int SMEM1 = (2 * 128 * (128 + 8) + 2 * 3 * 128 * 72) * 2;  // 180224
    constexpr int SMEM2 = (2 * 128 * (64 + 8)  + 2 * 3 * 64  * 72) * 2;  // 92160
    cudaFuncSetAttribute(gemm_tc2_kernel<128, false>,
                         cudaFuncAttributeMaxDynamicSharedMemorySize, SMEM1);
    cudaFuncSetAttribute(gemm_tc2_kernel<64, true>,
                         cudaFuncAttributeMaxDynamicSharedMemorySize, SMEM2);

    int gemmBlocks = (N + 127) / 128;
    int nodeBlocks = (N + 255) / 256;
    int edgeBlocks = (E + 255) / 256;
    int gatherBlocks = (N * 32 + 255) / 256;

    // --- weight pre-split + CSR build ---
    presplit_kernel<<<(36864 + 255) / 256, 256>>>(W1, L1, W2, L2);
    zero_cnt_kernel<<<nodeBlocks, 256>>>(N);
    hist_kernel<<<edgeBlocks, 256>>>(dst, E);
    scan_kernel<<<1, 1024>>>(N);
    fill_kernel<<<edgeBlocks, 256>>>(src, dst, et, E);

    // --- layer 1 ---
    gemm_tc2_kernel<128, false><<<gemmBlocks, 256, SMEM1>>>(x, N,
        w1h, w1l, b1, tx, tx + (long)N * 64, bufA);
    gather64_kernel<<<gatherBlocks, 256>>>(tx, bufA, N);

    // --- layer 2 ---
    gemm_tc2_kernel<64, true><<<gemmBlocks, 256, SMEM2>>>(bufA, N,
        w2h, w2l, b2, tx, tx + (long)N * 64, bufB);
    gather64_kernel<<<gatherBlocks, 256>>>(tx, bufB, N);

    // --- layer 3 ---
    layer3_kernel<<<nodeBlocks, 256>>>(bufB, W3, L3, b3, ev, out, N);
    gather2_kernel<<<nodeBlocks, 256>>>(ev, out, N);

    // --- global min then action mask ---
    min_kernel<<<160, 256>>>(out, N * 2);
    mask_kernel<<<nodeBlocks, 256>>>(out, cs, ms, N);
}

// round 5
// speedup vs baseline: 1.3542x; 1.3542x over previous
#include <cuda_runtime.h>
#include <cuda_bf16.h>
#include <cstdint>

#define MAX_N 50000
#define MAX_E 800000
#define HDIM  64

// ---------------- scratch (no allocations allowed) ----------------
__device__ float g_tx[2L * MAX_N * HDIM];   // [2][N][64] per-relation transforms
__device__ float g_bufA[MAX_N * HDIM];
__device__ float g_bufB[MAX_N * HDIM];
__device__ float g_ev[2L * MAX_N * 2];      // [2][N][2] layer-3 messages
__device__ int   g_cnt[MAX_N];
__device__ int   g_off[MAX_N + 1];
__device__ int   g_pos[MAX_N];
__device__ int   g_bsum[64];                // per-block sums for hierarchical scan
__device__ int   g_bpre[64];                // exclusive prefixes of block sums
__device__ unsigned g_elist[MAX_E];         // packed: src | (etype<<16)   (src < 65536)
__device__ unsigned g_min_key;
// pre-split bf16 weights: [3][K][64] hi/lo per layer
__device__ __nv_bfloat16 g_w1h[3 * 128 * 64], g_w1l[3 * 128 * 64];
__device__ __nv_bfloat16 g_w2h[3 * 64 * 64],  g_w2l[3 * 64 * 64];

// monotone float<->uint encoding so atomicMin(uint) == float min
__device__ __forceinline__ unsigned fenc(float f) {
    unsigned b = __float_as_uint(f);
    return (b & 0x80000000u) ? ~b : (b | 0x80000000u);
}
__device__ __forceinline__ float fdec(unsigned k) {
    unsigned b = (k & 0x80000000u) ? (k ^ 0x80000000u) : ~k;
    return __uint_as_float(b);
}
__device__ __forceinline__ void split_bf16(float v, __nv_bfloat16& h, __nv_bfloat16& l) {
    h = __float2bfloat16(v);
    l = __float2bfloat16(v - __bfloat162float(h));
}

// ================= weight pre-split =================
__global__ void presplit_kernel(const float* __restrict__ W1, const float* __restrict__ L1,
                                const float* __restrict__ W2, const float* __restrict__ L2)
{
    int i = blockIdx.x * blockDim.x + threadIdx.x;
    if (i < 24576) {
        float v = (i < 16384) ? W1[i] : L1[i - 16384];
        split_bf16(v, g_w1h[i], g_w1l[i]);
    } else if (i < 24576 + 12288) {
        int j = i - 24576;
        float v = (j < 8192) ? W2[j] : L2[j - 8192];
        split_bf16(v, g_w2h[j], g_w2l[j]);
    }
}

// ================= CSR build =================
__global__ void zero_cnt_kernel(int N) {
    int i = blockIdx.x * blockDim.x + threadIdx.x;
    if (i < N) g_cnt[i] = 0;
    if (i == 0) g_min_key = 0xFFFFFFFFu;
}

__global__ void hist_kernel(const int* __restrict__ dst, int E) {
    int e = blockIdx.x * blockDim.x + threadIdx.x;
    if (e < E) atomicAdd(&g_cnt[dst[e]], 1);
}

// ---- 3-stage hierarchical exclusive scan ----
// stage 1: per-block (1024 elems) local exclusive scan into g_off, block sum out
__global__ void __launch_bounds__(1024) scan1_kernel(int N) {
    __shared__ int sa[1024], sb[1024];
    const int tid = threadIdx.x;
    const int i = blockIdx.x * 1024 + tid;
    int v = (i < N) ? g_cnt[i] : 0;
    sa[tid] = v;
    __syncthreads();
    int* in = sa; int* out = sb;
    #pragma unroll
    for (int o = 1; o < 1024; o <<= 1) {
        out[tid] = in[tid] + (tid >= o ? in[tid - o] : 0);
        __syncthreads();
        int* t = in; in = out; out = t;
    }
    if (i < N) g_off[i] = in[tid] - v;        // local exclusive prefix
    if (tid == 1023) g_bsum[blockIdx.x] = in[1023];
}

// stage 2: single tiny block scans block sums
__global__ void scan2_kernel(int nb) {
    __shared__ int s[64];
    int tid = threadIdx.x;
    s[tid] = (tid < nb) ? g_bsum[tid] : 0;
    __syncthreads();
    if (tid == 0) {
        int run = 0;
        for (int b = 0; b < nb; b++) { g_bpre[b] = run; run += s[b]; }
    }
}

// stage 3: add block prefix, emit g_off/g_pos (+ sentinel)
__global__ void scan3_kernel(int N, int E) {
    int i = blockIdx.x * blockDim.x + threadIdx.x;
    if (i < N) {
        int o = g_off[i] + g_bpre[i >> 10];
        g_off[i] = o;
        g_pos[i] = o;
    }
    if (i == 0) g_off[N] = E;
}

__global__ void fill_kernel(const int* __restrict__ src,
                            const int* __restrict__ dst,
                            const int* __restrict__ et, int E) {
    int e = blockIdx.x * blockDim.x + threadIdx.x;
    if (e >= E) return;
    int p = atomicAdd(&g_pos[dst[e]], 1);
    g_elist[p] = (unsigned)src[e] | ((unsigned)et[e] << 16);
}

// ================= tensor-core helpers =================
__device__ __forceinline__ void ldsm_x4(uint32_t* r, const void* p) {
    uint32_t a = (uint32_t)__cvta_generic_to_shared(p);
    asm volatile("ldmatrix.sync.aligned.m8n8.x4.shared.b16 {%0,%1,%2,%3}, [%4];"
        : "=r"(r[0]), "=r"(r[1]), "=r"(r[2]), "=r"(r[3]) : "r"(a));
}
__device__ __forceinline__ void ldsm_x2t(uint32_t* r, const void* p) {
    uint32_t a = (uint32_t)__cvta_generic_to_shared(p);
    asm volatile("ldmatrix.sync.aligned.m8n8.x2.trans.shared.b16 {%0,%1}, [%2];"
        : "=r"(r[0]), "=r"(r[1]) : "r"(a));
}
__device__ __forceinline__ void mma_bf16(float* c, const uint32_t* a, const uint32_t* b) {
    asm volatile("mma.sync.aligned.m16n8k16.row.col.f32.bf16.bf16.f32 "
        "{%0,%1,%2,%3}, {%4,%5,%6,%7}, {%8,%9}, {%0,%1,%2,%3};"
        : "+f"(c[0]), "+f"(c[1]), "+f"(c[2]), "+f"(c[3])
        : "r"(a[0]), "r"(a[1]), "r"(a[2]), "r"(a[3]), "r"(b[0]), "r"(b[1]));
}

// ================= tensor-core triple GEMM v2 (BM=128, pre-split weights) =================
template<int K, bool RELU_IN>
__global__ void __launch_bounds__(256, 1) gemm_tc2_kernel(
    const float* __restrict__ A, int M,
    const __nv_bfloat16* __restrict__ Wh, const __nv_bfloat16* __restrict__ Wl,
    const float* __restrict__ bias,
    float* __restrict__ C0, float* __restrict__ C1, float* __restrict__ Cl)
{
    constexpr int BM = 128;
    constexpr int AS = K + 8;
    constexpr int WS = 72;
    extern __shared__ __nv_bfloat16 sm[];
    __nv_bfloat16* Ahi = sm;
    __nv_bfloat16* Alo = Ahi + BM * AS;
    __nv_bfloat16* Whs = Alo + BM * AS;
    __nv_bfloat16* Wls = Whs + 3 * K * WS;

    const int tid  = threadIdx.x;
    const int lane = tid & 31;
    const int warp = tid >> 5;
    const int rowBase = blockIdx.x * BM;

    for (int u = tid; u < 3 * K * 8; u += 256) {
        int row = u >> 3, col = (u & 7) * 8;
        *(uint4*)&Whs[row * WS + col] = *(const uint4*)&Wh[row * 64 + col];
        *(uint4*)&Wls[row * WS + col] = *(const uint4*)&Wl[row * 64 + col];
    }
    for (int i = tid * 4; i < BM * K; i += 1024) {
        int r = i / K, kq = i % K;
        float4 v = make_float4(0.f, 0.f, 0.f, 0.f);
        if (rowBase + r < M) v = *(const float4*)&A[(long)(rowBase + r) * K + kq];
        float vv[4] = {v.x, v.y, v.z, v.w};
        #pragma unroll
        for (int j = 0; j < 4; j++) {
            float x = RELU_IN ? fmaxf(vv[j], 0.f) : vv[j];
            __nv_bfloat16 h, l;
            split_bf16(x, h, l);
            Ahi[r * AS + kq + j] = h;
            Alo[r * AS + kq + j] = l;
        }
    }
    __syncthreads();

    const int mw = (warp & 3) * 32;
    const int nw = (warp >> 2) * 96;
    const int lr = lane & 15;
    const int aCol = (lane >> 4) * 8;

    float acc[2][12][4];
    #pragma unroll
    for (int mt = 0; mt < 2; mt++)
        #pragma unroll
        for (int j = 0; j < 12; j++)
            #pragma unroll
            for (int q = 0; q < 4; q++) acc[mt][j][q] = 0.f;

    #pragma unroll
    for (int kk = 0; kk < K / 16; kk++) {
        uint32_t ah[2][4], al[2][4];
        #pragma unroll
        for (int mt = 0; mt < 2; mt++) {
            ldsm_x4(ah[mt], &Ahi[(mw + mt * 16 + lr) * AS + kk * 16 + aCol]);
            ldsm_x4(al[mt], &Alo[(mw + mt * 16 + lr) * AS + kk * 16 + aCol]);
        }
        #pragma unroll
        for (int j = 0; j < 12; j++) {
            int n = nw + j * 8;
            int w = n >> 6, nc = n & 63;
            long woff = (long)(w * K + kk * 16 + lr) * WS + nc;
            uint32_t bh[2], bl[2];
            ldsm_x2t(bh, &Whs[woff]);
            ldsm_x2t(bl, &Wls[woff]);
            mma_bf16(acc[0][j], ah[0], bh);
            mma_bf16(acc[0][j], ah[0], bl);
            mma_bf16(acc[0][j], al[0], bh);
            mma_bf16(acc[1][j], ah[1], bh);
            mma_bf16(acc[1][j], ah[1], bl);
            mma_bf16(acc[1][j], al[1], bh);
        }
    }

    float* Cs[3] = {C0, C1, Cl};
    #pragma unroll
    for (int mt = 0; mt < 2; mt++) {
        const int r0 = rowBase + mw + mt * 16 + (lane >> 2);
        #pragma unroll
        for (int j = 0; j < 12; j++) {
            int n = nw + j * 8;
            int w = n >> 6;
            int nc = (n & 63) + 2 * (lane & 3);
            float b0 = 0.f, b1 = 0.f;
            if (w == 2) { b0 = bias[nc]; b1 = bias[nc + 1]; }
            if (r0 < M)
                *(float2*)&Cs[w][(long)r0 * 64 + nc] =
                    make_float2(acc[mt][j][0] + b0, acc[mt][j][1] + b1);
            if (r0 + 8 < M)
                *(float2*)&Cs[w][(long)(r0 + 8) * 64 + nc] =
                    make_float2(acc[mt][j][2] + b0, acc[mt][j][3] + b1);
        }
    }
}

// ================= gather aggregation (CSR, MLP=4, no atomics) =================
__global__ void gather64_kernel(const float* __restrict__ t,
                                float* __restrict__ agg, int N)
{
    int w = (int)((blockIdx.x * (long)blockDim.x + threadIdx.x) >> 5);
    int lane = threadIdx.x & 31;
    if (w >= N) return;
    int beg = g_off[w], end = g_off[w + 1];
    long o = (long)w * 64 + lane * 2;
    float2 a0 = *(float2*)&agg[o];
    float2 a1 = make_float2(0.f, 0.f), a2 = a1, a3 = a1;
    int e = beg;
    for (; e + 4 <= end; e += 4) {
        unsigned p0 = g_elist[e],     p1 = g_elist[e + 1];
        unsigned p2 = g_elist[e + 2], p3 = g_elist[e + 3];
        float2 v0 = *(const float2*)&t[(long)((p0 >> 16) * N + (p0 & 0xFFFFu)) * 64 + lane * 2];
        float2 v1 = *(const float2*)&t[(long)((p1 >> 16) * N + (p1 & 0xFFFFu)) * 64 + lane * 2];
        float2 v2 = *(const float2*)&t[(long)((p2 >> 16) * N + (p2 & 0xFFFFu)) * 64 + lane * 2];
        float2 v3 = *(const float2*)&t[(long)((p3 >> 16) * N + (p3 & 0xFFFFu)) * 64 + lane * 2];
        a0.x += v0.x; a0.y += v0.y;
        a1.x += v1.x; a1.y += v1.y;
        a2.x += v2.x; a2.y += v2.y;
        a3.x += v3.x; a3.y += v3.y;
    }
    for (; e < end; e++) {
        unsigned p = g_elist[e];
        float2 v = *(const float2*)&t[(long)((p >> 16) * N + (p & 0xFFFFu)) * 64 + lane * 2];
        a0.x += v.x; a0.y += v.y;
    }
    a0.x += a1.x + a2.x + a3.x;
    a0.y += a1.y + a2.y + a3.y;
    *(float2*)&agg[o] = a0;
}

__global__ void gather2_kernel(const float* __restrict__ ev,
                               float* __restrict__ out, int N)
{
    int n = blockIdx.x * blockDim.x + threadIdx.x;
    if (n >= N) return;
    int beg = g_off[n], end = g_off[n + 1];
    float2 a0 = *(float2*)&out[n * 2];
    float2 a1 = make_float2(0.f, 0.f), a2 = a1, a3 = a1;
    int e = beg;
    for (; e + 4 <= end; e += 4) {
        unsigned p0 = g_elist[e],     p1 = g_elist[e + 1];
        unsigned p2 = g_elist[e + 2], p3 = g_elist[e + 3];
        float2 v0 = *(const float2*)&ev[(long)((p0 >> 16) * N + (p0 & 0xFFFFu)) * 2];
        float2 v1 = *(const float2*)&ev[(long)((p1 >> 16) * N + (p1 & 0xFFFFu)) * 2];
        float2 v2 = *(const float2*)&ev[(long)((p2 >> 16) * N + (p2 & 0xFFFFu)) * 2];
        float2 v3 = *(const float2*)&ev[(long)((p3 >> 16) * N + (p3 & 0xFFFFu)) * 2];
        a0.x += v0.x; a0.y += v0.y;
        a1.x += v1.x; a1.y += v1.y;
        a2.x += v2.x; a2.y += v2.y;
        a3.x += v3.x; a3.y += v3.y;
    }
    for (; e < end; e++) {
        unsigned p = g_elist[e];
        float2 v = *(const float2*)&ev[(long)((p >> 16) * N + (p & 0xFFFFu)) * 2];
        a0.x += v.x; a0.y += v.y;
    }
    a0.x += a1.x + a2.x + a3.x;
    a0.y += a1.y + a2.y + a3.y;
    *(float2*)&out[n * 2] = a0;
}

// ================= layer 3 per-node transforms =================
__global__ void layer3_kernel(
    const float* __restrict__ H,
    const float* __restrict__ W3, const float* __restrict__ L3,
    const float* __restrict__ b3,
    float* __restrict__ ev, float* __restrict__ out, int N)
{
    __shared__ float sW0[128], sW1[128], sL[128], sb[2];
    int tid = threadIdx.x;
    for (int i = tid; i < 128; i += blockDim.x) {
        sW0[i] = W3[i];
        sW1[i] = W3[128 + i];
        sL[i]  = L3[i];
    }
    if (tid < 2) sb[tid] = b3[tid];
    __syncthreads();

    int n = blockIdx.x * blockDim.x + tid;
    if (n >= N) return;
    const float* h = &H[(long)n * 64];
    float a0 = 0.f, a1 = 0.f, c0 = 0.f, c1 = 0.f, l0 = 0.f, l1 = 0.f;
    #pragma unroll
    for (int k = 0; k < 64; k += 4) {
        float4 hv = *(const float4*)&h[k];
        float xv[4] = {fmaxf(hv.x, 0.f), fmaxf(hv.y, 0.f),
                       fmaxf(hv.z, 0.f), fmaxf(hv.w, 0.f)};
        #pragma unroll
        for (int j = 0; j < 4; j++) {
            int kk = k + j;
            a0 = fmaf(xv[j], sW0[kk * 2 + 0], a0);
            a1 = fmaf(xv[j], sW0[kk * 2 + 1], a1);
            c0 = fmaf(xv[j], sW1[kk * 2 + 0], c0);
            c1 = fmaf(xv[j], sW1[kk * 2 + 1], c1);
            l0 = fmaf(xv[j], sL[kk * 2 + 0], l0);
            l1 = fmaf(xv[j], sL[kk * 2 + 1], l1);
        }
    }
    *(float2*)&ev[n * 2] = make_float2(a0, a1);
    *(float2*)&ev[((long)N + n) * 2] = make_float2(c0, c1);
    *(float2*)&out[n * 2] = make_float2(l0 + sb[0], l1 + sb[1]);
}

// ================= global min + mask =================
__global__ void min_kernel(const float* __restrict__ v, int n)
{
    float m = 3.402823466e+38f;
    for (int i = blockIdx.x * blockDim.x + threadIdx.x; i < n;
         i += gridDim.x * blockDim.x)
        m = fminf(m, v[i]);
    #pragma unroll
    for (int o = 16; o; o >>= 1)
        m = fminf(m, __shfl_xor_sync(0xffffffffu, m, o));
    __shared__ float sm[8];
    if ((threadIdx.x & 31) == 0) sm[threadIdx.x >> 5] = m;
    __syncthreads();
    if (threadIdx.x < 8) {
        m = sm[threadIdx.x];
        #pragma unroll
        for (int o = 4; o; o >>= 1)
            m = fminf(m, __shfl_xor_sync(0xffu, m, o));
        if (threadIdx.x == 0) atomicMin(&g_min_key, fenc(m));
    }
}

__global__ void mask_kernel(float* __restrict__ out,
                            const int* __restrict__ cs,
                            const int* __restrict__ ms, int N)
{
    int n = blockIdx.x * blockDim.x + threadIdx.x;
    if (n >= N) return;
    float mn = fdec(g_min_key) - 1.0f;
    float2 v = *(float2*)&out[n * 2];
    if (cs[n] >= ms[n] - 1) v.x = mn;
    if (cs[n] == 0)         v.y = mn;
    *(float2*)&out[n * 2] = v;
}

// ================= launch =================
extern "C" void kernel_launch(void* const* d_in, const int* in_sizes, int n_in,
                              void* d_out, int out_size)
{
    const float* x  = (const float*)d_in[0];
    const int* src  = (const int*)d_in[1];
    const int* dst  = (const int*)d_in[2];
    const int* et   = (const int*)d_in[3];
    const int* cs   = (const int*)d_in[4];
    const int* ms   = (const int*)d_in[5];
    const float* W1 = (const float*)d_in[6];
    const float* L1 = (const float*)d_in[7];
    const float* b1 = (const float*)d_in[8];
    const float* W2 = (const float*)d_in[9];
    const float* L2 = (const float*)d_in[10];
    const float* b2 = (const float*)d_in[11];
    const float* W3 = (const float*)d_in[12];
    const float* L3 = (const float*)d_in[13];
    const float* b3 = (const float*)d_in[14];

    const int N = in_sizes[0] / 128;
    const int E = in_sizes[1];
    float* out = (float*)d_out;

    float *tx, *bufA, *bufB, *ev;
    __nv_bfloat16 *w1h, *w1l, *w2h, *w2l;
    cudaGetSymbolAddress((void**)&tx,   g_tx);
    cudaGetSymbolAddress((void**)&bufA, g_bufA);
    cudaGetSymbolAddress((void**)&bufB, g_bufB);
    cudaGetSymbolAddress((void**)&ev,   g_ev);
    cudaGetSymbolAddress((void**)&w1h,  g_w1h);
    cudaGetSymbolAddress((void**)&w1l,  g_w1l);
    cudaGetSymbolAddress((void**)&w2h,  g_w2h);
    cudaGetSymbolAddress((void**)&w2l,  g_w2l);

    constexpr int SMEM1 = (2 * 128 * (128 + 8) + 2 * 3 * 128 * 72) * 2;  // 180224
    constexpr int SMEM2 = (2 * 128 * (64 + 8)  + 2 * 3 * 64  * 72) * 2;  // 92160
    cudaFuncSetAttribute(gemm_tc2_kernel<128, false>,
                         cudaFuncAttributeMaxDynamicSharedMemorySize, SMEM1);
    cudaFuncSetAttribute(gemm_tc2_kernel<64, true>,
                         cudaFuncAttributeMaxDynamicSharedMemorySize, SMEM2);

    int gemmBlocks = (N + 127) / 128;
    int nodeBlocks = (N + 255) / 256;
    int edgeBlocks = (E + 255) / 256;
    int gatherBlocks = (N * 32 + 255) / 256;
    int scanBlocks = (N + 1023) / 1024;

    // --- weight pre-split + CSR build ---
    presplit_kernel<<<(36864 + 255) / 256, 256>>>(W1, L1, W2, L2);
    zero_cnt_kernel<<<nodeBlocks, 256>>>(N);
    hist_kernel<<<edgeBlocks, 256>>>(dst, E);
    scan1_kernel<<<scanBlocks, 1024>>>(N);
    scan2_kernel<<<1, 64>>>(scanBlocks);
    scan3_kernel<<<(N + 255) / 256, 256>>>(N, E);
    fill_kernel<<<edgeBlocks, 256>>>(src, dst, et, E);

    // --- layer 1 ---
    gemm_tc2_kernel<128, false><<<gemmBlocks, 256, SMEM1>>>(x, N,
        w1h, w1l, b1, tx, tx + (long)N * 64, bufA);
    gather64_kernel<<<gatherBlocks, 256>>>(tx, bufA, N);

    // --- layer 2 ---
    gemm_tc2_kernel<64, true><<<gemmBlocks, 256, SMEM2>>>(bufA, N,
        w2h, w2l, b2, tx, tx + (long)N * 64, bufB);
    gather64_kernel<<<gatherBlocks, 256>>>(tx, bufB, N);

    // --- layer 3 ---
    layer3_kernel<<<nodeBlocks, 256>>>(bufB, W3, L3, b3, ev, out, N);
    gather2_kernel<<<nodeBlocks, 256>>>(ev, out, N);

    // --- global min then action mask ---
    min_kernel<<<160, 256>>>(out, N * 2);
    mask_kernel<<<nodeBlocks, 256>>>(out, cs, ms, N);
}

// round 6
// speedup vs baseline: 1.3953x; 1.0303x over previous
#include <cuda_runtime.h>
#include <cuda_bf16.h>
#include <cstdint>

#define MAX_N 50000
#define MAX_E 800000
#define HDIM  64

// ---------------- scratch (no allocations allowed) ----------------
__device__ float g_tx[2L * MAX_N * HDIM];   // [2][N][64] per-relation transforms
__device__ float g_bufA[MAX_N * HDIM];
__device__ float g_bufB[MAX_N * HDIM];      // layer-2 self-loop output (gather2 input)
__device__ float g_ev[2L * MAX_N * 2];      // [2][N][2] layer-3 messages
__device__ int   g_cnt[MAX_N];
__device__ int   g_off[MAX_N + 1];
__device__ int   g_pos[MAX_N];
__device__ int   g_bsum[64];                // block sums; -1 = not ready (sentinel)
__device__ unsigned g_elist[MAX_E];         // packed: src | (etype<<16)   (src < 65536)
__device__ unsigned g_min_key;
// pre-split bf16 weights: [3][K][64] hi/lo per layer
__device__ __nv_bfloat16 g_w1h[3 * 128 * 64], g_w1l[3 * 128 * 64];
__device__ __nv_bfloat16 g_w2h[3 * 64 * 64],  g_w2l[3 * 64 * 64];

// monotone float<->uint encoding so atomicMin(uint) == float min
__device__ __forceinline__ unsigned fenc(float f) {
    unsigned b = __float_as_uint(f);
    return (b & 0x80000000u) ? ~b : (b | 0x80000000u);
}
__device__ __forceinline__ float fdec(unsigned k) {
    unsigned b = (k & 0x80000000u) ? (k ^ 0x80000000u) : ~k;
    return __uint_as_float(b);
}
__device__ __forceinline__ void split_bf16(float v, __nv_bfloat16& h, __nv_bfloat16& l) {
    h = __float2bfloat16(v);
    l = __float2bfloat16(v - __bfloat162float(h));
}

// ================= setup: presplit weights + zero counters + sentinels =================
__global__ void setup_kernel(const float* __restrict__ W1, const float* __restrict__ L1,
                             const float* __restrict__ W2, const float* __restrict__ L2,
                             int N)
{
    int i = blockIdx.x * blockDim.x + threadIdx.x;
    if (i < 24576) {
        float v = (i < 16384) ? W1[i] : L1[i - 16384];
        split_bf16(v, g_w1h[i], g_w1l[i]);
    } else if (i < 36864) {
        int j = i - 24576;
        float v = (j < 8192) ? W2[j] : L2[j - 8192];
        split_bf16(v, g_w2h[j], g_w2l[j]);
    }
    if (i < N) g_cnt[i] = 0;
    if (i < 64) g_bsum[i] = -1;
    if (i == 0) g_min_key = 0xFFFFFFFFu;
}

// ================= CSR build =================
__global__ void hist_kernel(const int* __restrict__ dst, int E) {
    int e = blockIdx.x * blockDim.x + threadIdx.x;
    if (e < E) atomicAdd(&g_cnt[dst[e]], 1);
}

// single-kernel exclusive scan with parallel lookback (49 blocks, sentinel -1)
__global__ void __launch_bounds__(1024) scan_kernel(int N, int E) {
    __shared__ int sa[1024], sb[1024];
    __shared__ int bpre;
    const int tid = threadIdx.x;
    const int i = blockIdx.x * 1024 + tid;
    int v = (i < N) ? g_cnt[i] : 0;
    sa[tid] = v;
    __syncthreads();
    int* in = sa; int* out = sb;
    #pragma unroll
    for (int o = 1; o < 1024; o <<= 1) {
        out[tid] = in[tid] + (tid >= o ? in[tid - o] : 0);
        __syncthreads();
        int* t = in; in = out; out = t;
    }
    // publish block total (single volatile word; -1 sentinel means not ready)
    if (tid == 1023)
        ((volatile int*)g_bsum)[blockIdx.x] = in[1023];
    // warp 0: sum all predecessor block totals (parallel lookback)
    if (tid < 32) {
        int run = 0;
        for (int base = 0; base < blockIdx.x; base += 32) {
            int idx = base + tid;
            int bv = 0;
            if (idx < blockIdx.x) {
                do { bv = ((volatile int*)g_bsum)[idx]; } while (bv < 0);
            }
            #pragma unroll
            for (int o = 16; o; o >>= 1) bv += __shfl_xor_sync(0xffffffffu, bv, o);
            run += bv;
        }
        if (tid == 0) bpre = run;
    }
    __syncthreads();
    if (i < N) {
        int o = bpre + in[tid] - v;   // exclusive prefix
        g_off[i] = o;
        g_pos[i] = o;
    }
    if (i == 0) g_off[N] = E;
}

__global__ void fill_kernel(const int* __restrict__ src,
                            const int* __restrict__ dst,
                            const int* __restrict__ et, int E) {
    int e = blockIdx.x * blockDim.x + threadIdx.x;
    if (e >= E) return;
    int p = atomicAdd(&g_pos[dst[e]], 1);
    g_elist[p] = (unsigned)src[e] | ((unsigned)et[e] << 16);
}

// ================= tensor-core helpers =================
__device__ __forceinline__ void ldsm_x4(uint32_t* r, const void* p) {
    uint32_t a = (uint32_t)__cvta_generic_to_shared(p);
    asm volatile("ldmatrix.sync.aligned.m8n8.x4.shared.b16 {%0,%1,%2,%3}, [%4];"
        : "=r"(r[0]), "=r"(r[1]), "=r"(r[2]), "=r"(r[3]) : "r"(a));
}
__device__ __forceinline__ void ldsm_x2t(uint32_t* r, const void* p) {
    uint32_t a = (uint32_t)__cvta_generic_to_shared(p);
    asm volatile("ldmatrix.sync.aligned.m8n8.x2.trans.shared.b16 {%0,%1}, [%2];"
        : "=r"(r[0]), "=r"(r[1]) : "r"(a));
}
__device__ __forceinline__ void mma_bf16(float* c, const uint32_t* a, const uint32_t* b) {
    asm volatile("mma.sync.aligned.m16n8k16.row.col.f32.bf16.bf16.f32 "
        "{%0,%1,%2,%3}, {%4,%5,%6,%7}, {%8,%9}, {%0,%1,%2,%3};"
        : "+f"(c[0]), "+f"(c[1]), "+f"(c[2]), "+f"(c[3])
        : "r"(a[0]), "r"(a[1]), "r"(a[2]), "r"(a[3]), "r"(b[0]), "r"(b[1]));
}

// ================= tensor-core triple GEMM v2 (BM=128, pre-split weights) =================
template<int K, bool RELU_IN>
__global__ void __launch_bounds__(256, 1) gemm_tc2_kernel(
    const float* __restrict__ A, int M,
    const __nv_bfloat16* __restrict__ Wh, const __nv_bfloat16* __restrict__ Wl,
    const float* __restrict__ bias,
    float* __restrict__ C0, float* __restrict__ C1, float* __restrict__ Cl)
{
    constexpr int BM = 128;
    constexpr int AS = K + 8;
    constexpr int WS = 72;
    extern __shared__ __nv_bfloat16 sm[];
    __nv_bfloat16* Ahi = sm;
    __nv_bfloat16* Alo = Ahi + BM * AS;
    __nv_bfloat16* Whs = Alo + BM * AS;
    __nv_bfloat16* Wls = Whs + 3 * K * WS;

    const int tid  = threadIdx.x;
    const int lane = tid & 31;
    const int warp = tid >> 5;
    const int rowBase = blockIdx.x * BM;

    for (int u = tid; u < 3 * K * 8; u += 256) {
        int row = u >> 3, col = (u & 7) * 8;
        *(uint4*)&Whs[row * WS + col] = *(const uint4*)&Wh[row * 64 + col];
        *(uint4*)&Wls[row * WS + col] = *(const uint4*)&Wl[row * 64 + col];
    }
    for (int i = tid * 4; i < BM * K; i += 1024) {
        int r = i / K, kq = i % K;
        float4 v = make_float4(0.f, 0.f, 0.f, 0.f);
        if (rowBase + r < M) v = *(const float4*)&A[(long)(rowBase + r) * K + kq];
        float vv[4] = {v.x, v.y, v.z, v.w};
        #pragma unroll
        for (int j = 0; j < 4; j++) {
            float x = RELU_IN ? fmaxf(vv[j], 0.f) : vv[j];
            __nv_bfloat16 h, l;
            split_bf16(x, h, l);
            Ahi[r * AS + kq + j] = h;
            Alo[r * AS + kq + j] = l;
        }
    }
    __syncthreads();

    const int mw = (warp & 3) * 32;
    const int nw = (warp >> 2) * 96;
    const int lr = lane & 15;
    const int aCol = (lane >> 4) * 8;

    float acc[2][12][4];
    #pragma unroll
    for (int mt = 0; mt < 2; mt++)
        #pragma unroll
        for (int j = 0; j < 12; j++)
            #pragma unroll
            for (int q = 0; q < 4; q++) acc[mt][j][q] = 0.f;

    #pragma unroll
    for (int kk = 0; kk < K / 16; kk++) {
        uint32_t ah[2][4], al[2][4];
        #pragma unroll
        for (int mt = 0; mt < 2; mt++) {
            ldsm_x4(ah[mt], &Ahi[(mw + mt * 16 + lr) * AS + kk * 16 + aCol]);
            ldsm_x4(al[mt], &Alo[(mw + mt * 16 + lr) * AS + kk * 16 + aCol]);
        }
        #pragma unroll
        for (int j = 0; j < 12; j++) {
            int n = nw + j * 8;
            int w = n >> 6, nc = n & 63;
            long woff = (long)(w * K + kk * 16 + lr) * WS + nc;
            uint32_t bh[2], bl[2];
            ldsm_x2t(bh, &Whs[woff]);
            ldsm_x2t(bl, &Wls[woff]);
            mma_bf16(acc[0][j], ah[0], bh);
            mma_bf16(acc[0][j], ah[0], bl);
            mma_bf16(acc[0][j], al[0], bh);
            mma_bf16(acc[1][j], ah[1], bh);
            mma_bf16(acc[1][j], ah[1], bl);
            mma_bf16(acc[1][j], al[1], bh);
        }
    }

    float* Cs[3] = {C0, C1, Cl};
    #pragma unroll
    for (int mt = 0; mt < 2; mt++) {
        const int r0 = rowBase + mw + mt * 16 + (lane >> 2);
        #pragma unroll
        for (int j = 0; j < 12; j++) {
            int n = nw + j * 8;
            int w = n >> 6;
            int nc = (n & 63) + 2 * (lane & 3);
            float b0 = 0.f, b1 = 0.f;
            if (w == 2) { b0 = bias[nc]; b1 = bias[nc + 1]; }
            if (r0 < M)
                *(float2*)&Cs[w][(long)r0 * 64 + nc] =
                    make_float2(acc[mt][j][0] + b0, acc[mt][j][1] + b1);
            if (r0 + 8 < M)
                *(float2*)&Cs[w][(long)(r0 + 8) * 64 + nc] =
                    make_float2(acc[mt][j][2] + b0, acc[mt][j][3] + b1);
        }
    }
}

// ================= gather64: one warp per node, MLP=4 =================
// FINAL=false: agg[n] += messages (layer-1 use).
// FINAL=true : h = agg + messages; relu(h); layer-3 matvecs -> ev, out (self part).
template<bool FINAL>
__global__ void gather64_kernel(const float* __restrict__ t,
                                float* __restrict__ agg, int N,
                                const float* __restrict__ W3,
                                const float* __restrict__ L3,
                                const float* __restrict__ b3,
                                float* __restrict__ ev,
                                float* __restrict__ out)
{
    __shared__ float sW0[128], sW1[128], sL[128], sb[2];
    if (FINAL) {
        int tid = threadIdx.x;
        for (int i = tid; i < 128; i += blockDim.x) {
            sW0[i] = W3[i];
            sW1[i] = W3[128 + i];
            sL[i]  = L3[i];
        }
        if (tid < 2) sb[tid] = b3[tid];
        __syncthreads();
    }

    int w = (int)((blockIdx.x * (long)blockDim.x + threadIdx.x) >> 5);
    int lane = threadIdx.x & 31;
    if (w >= N) return;
    int beg = g_off[w], end = g_off[w + 1];
    long o = (long)w * 64 + lane * 2;
    float2 a0 = *(float2*)&agg[o];          // self-loop (+bias) already there
    float2 a1 = make_float2(0.f, 0.f), a2 = a1, a3 = a1;
    int e = beg;
    for (; e + 4 <= end; e += 4) {
        unsigned p0 = g_elist[e],     p1 = g_elist[e + 1];
        unsigned p2 = g_elist[e + 2], p3 = g_elist[e + 3];
        float2 v0 = *(const float2*)&t[(long)((p0 >> 16) * N + (p0 & 0xFFFFu)) * 64 + lane * 2];
        float2 v1 = *(const float2*)&t[(long)((p1 >> 16) * N + (p1 & 0xFFFFu)) * 64 + lane * 2];
        float2 v2 = *(const float2*)&t[(long)((p2 >> 16) * N + (p2 & 0xFFFFu)) * 64 + lane * 2];
        float2 v3 = *(const float2*)&t[(long)((p3 >> 16) * N + (p3 & 0xFFFFu)) * 64 + lane * 2];
        a0.x += v0.x; a0.y += v0.y;
        a1.x += v1.x; a1.y += v1.y;
        a2.x += v2.x; a2.y += v2.y;
        a3.x += v3.x; a3.y += v3.y;
    }
    for (; e < end; e++) {
        unsigned p = g_elist[e];
        float2 v = *(const float2*)&t[(long)((p >> 16) * N + (p & 0xFFFFu)) * 64 + lane * 2];
        a0.x += v.x; a0.y += v.y;
    }
    a0.x += a1.x + a2.x + a3.x;
    a0.y += a1.y + a2.y + a3.y;

    if (!FINAL) {
        *(float2*)&agg[o] = a0;
        return;
    }

    // layer 3 fused: relu + three 64->2 matvecs via warp reduction
    float x0 = fmaxf(a0.x, 0.f), x1 = fmaxf(a0.y, 0.f);
    int k0 = lane * 2, k1 = lane * 2 + 1;
    float p0 = x0 * sW0[k0 * 2 + 0] + x1 * sW0[k1 * 2 + 0];
    float p1 = x0 * sW0[k0 * 2 + 1] + x1 * sW0[k1 * 2 + 1];
    float p2 = x0 * sW1[k0 * 2 + 0] + x1 * sW1[k1 * 2 + 0];
    float p3 = x0 * sW1[k0 * 2 + 1] + x1 * sW1[k1 * 2 + 1];
    float p4 = x0 * sL[k0 * 2 + 0]  + x1 * sL[k1 * 2 + 0];
    float p5 = x0 * sL[k0 * 2 + 1]  + x1 * sL[k1 * 2 + 1];
    #pragma unroll
    for (int off = 16; off; off >>= 1) {
        p0 += __shfl_xor_sync(0xffffffffu, p0, off);
        p1 += __shfl_xor_sync(0xffffffffu, p1, off);
        p2 += __shfl_xor_sync(0xffffffffu, p2, off);
        p3 += __shfl_xor_sync(0xffffffffu, p3, off);
        p4 += __shfl_xor_sync(0xffffffffu, p4, off);
        p5 += __shfl_xor_sync(0xffffffffu, p5, off);
    }
    if (lane == 0) {
        *(float2*)&ev[(long)w * 2]           = make_float2(p0, p1);
        *(float2*)&ev[((long)N + w) * 2]     = make_float2(p2, p3);
        *(float2*)&out[(long)w * 2]          = make_float2(p4 + sb[0], p5 + sb[1]);
    }
}

// ================= ev-gather + global min (fused) =================
__global__ void gatherev_min_kernel(const float* __restrict__ ev,
                                    float* __restrict__ out, int N)
{
    int n = blockIdx.x * blockDim.x + threadIdx.x;
    float m = 3.402823466e+38f;
    if (n < N) {
        int beg = g_off[n], end = g_off[n + 1];
        float2 a0 = *(float2*)&out[n * 2];
        float2 a1 = make_float2(0.f, 0.f), a2 = a1, a3 = a1;
        int e = beg;
        for (; e + 4 <= end; e += 4) {
            unsigned p0 = g_elist[e],     p1 = g_elist[e + 1];
            unsigned p2 = g_elist[e + 2], p3 = g_elist[e + 3];
            float2 v0 = *(const float2*)&ev[(long)((p0 >> 16) * N + (p0 & 0xFFFFu)) * 2];
            float2 v1 = *(const float2*)&ev[(long)((p1 >> 16) * N + (p1 & 0xFFFFu)) * 2];
            float2 v2 = *(const float2*)&ev[(long)((p2 >> 16) * N + (p2 & 0xFFFFu)) * 2];
            float2 v3 = *(const float2*)&ev[(long)((p3 >> 16) * N + (p3 & 0xFFFFu)) * 2];
            a0.x += v0.x; a0.y += v0.y;
            a1.x += v1.x; a1.y += v1.y;
            a2.x += v2.x; a2.y += v2.y;
            a3.x += v3.x; a3.y += v3.y;
        }
        for (; e < end; e++) {
            unsigned p = g_elist[e];
            float2 v = *(const float2*)&ev[(long)((p >> 16) * N + (p & 0xFFFFu)) * 2];
            a0.x += v.x; a0.y += v.y;
        }
        a0.x += a1.x + a2.x + a3.x;
        a0.y += a1.y + a2.y + a3.y;
        *(float2*)&out[n * 2] = a0;
        m = fminf(a0.x, a0.y);
    }
    // block min -> atomicMin
    #pragma unroll
    for (int o = 16; o; o >>= 1)
        m = fminf(m, __shfl_xor_sync(0xffffffffu, m, o));
    __shared__ float sm[8];
    if ((threadIdx.x & 31) == 0) sm[threadIdx.x >> 5] = m;
    __syncthreads();
    if (threadIdx.x < 8) {
        m = sm[threadIdx.x];
        #pragma unroll
        for (int o = 4; o; o >>= 1)
            m = fminf(m, __shfl_xor_sync(0xffu, m, o));
        if (threadIdx.x == 0) atomicMin(&g_min_key, fenc(m));
    }
}

__global__ void mask_kernel(float* __restrict__ out,
                            const int* __restrict__ cs,
                            const int* __restrict__ ms, int N)
{
    int n = blockIdx.x * blockDim.x + threadIdx.x;
    if (n >= N) return;
    float mn = fdec(g_min_key) - 1.0f;
    float2 v = *(float2*)&out[n * 2];
    if (cs[n] >= ms[n] - 1) v.x = mn;
    if (cs[n] == 0)         v.y = mn;
    *(float2*)&out[n * 2] = v;
}

// ================= launch =================
extern "C" void kernel_launch(void* const* d_in, const int* in_sizes, int n_in,
                              void* d_out, int out_size)
{
    const float* x  = (const float*)d_in[0];
    const int* src  = (const int*)d_in[1];
    const int* dst  = (const int*)d_in[2];
    const int* et   = (const int*)d_in[3];
    const int* cs   = (const int*)d_in[4];
    const int* ms   = (const int*)d_in[5];
    const float* W1 = (const float*)d_in[6];
    const float* L1 = (const float*)d_in[7];
    const float* b1 = (const float*)d_in[8];
    const float* W2 = (const float*)d_in[9];
    const float* L2 = (const float*)d_in[10];
    const float* b2 = (const float*)d_in[11];
    const float* W3 = (const float*)d_in[12];
    const float* L3 = (const float*)d_in[13];
    const float* b3 = (const float*)d_in[14];

    const int N = in_sizes[0] / 128;
    const int E = in_sizes[1];
    float* out = (float*)d_out;

    float *tx, *bufA, *bufB, *ev;
    __nv_bfloat16 *w1h, *w1l, *w2h, *w2l;
    cudaGetSymbolAddress((void**)&tx,   g_tx);
    cudaGetSymbolAddress((void**)&bufA, g_bufA);
    cudaGetSymbolAddress((void**)&bufB, g_bufB);
    cudaGetSymbolAddress((void**)&ev,   g_ev);
    cudaGetSymbolAddress((void**)&w1h,  g_w1h);
    cudaGetSymbolAddress((void**)&w1l,  g_w1l);
    cudaGetSymbolAddress((void**)&w2h,  g_w2h);
    cudaGetSymbolAddress((void**)&w2l,  g_w2l);

    constexpr int SMEM1 = (2 * 128 * (128 + 8) + 2 * 3 * 128 * 72) * 2;  // 180224
    constexpr int SMEM2 = (2 * 128 * (64 + 8)  + 2 * 3 * 64  * 72) * 2;  // 92160
    cudaFuncSetAttribute(gemm_tc2_kernel<128, false>,
                         cudaFuncAttributeMaxDynamicSharedMemorySize, SMEM1);
    cudaFuncSetAttribute(gemm_tc2_kernel<64, true>,
                         cudaFuncAttributeMaxDynamicSharedMemorySize, SMEM2);

    int gemmBlocks = (N + 127) / 128;
    int nodeBlocks = (N + 255) / 256;
    int edgeBlocks = (E + 255) / 256;
    int gatherBlocks = (N * 32 + 255) / 256;
    int scanBlocks = (N + 1023) / 1024;

    // --- setup (presplit + zero + sentinels) + CSR build ---
    setup_kernel<<<nodeBlocks, 256>>>(W1, L1, W2, L2, N);
    hist_kernel<<<edgeBlocks, 256>>>(dst, E);
    scan_kernel<<<scanBlocks, 1024>>>(N, E);
    fill_kernel<<<edgeBlocks, 256>>>(src, dst, et, E);

    // --- layer 1 ---
    gemm_tc2_kernel<128, false><<<gemmBlocks, 256, SMEM1>>>(x, N,
        w1h, w1l, b1, tx, tx + (long)N * 64, bufA);
    gather64_kernel<false><<<gatherBlocks, 256>>>(tx, bufA, N,
        nullptr, nullptr, nullptr, nullptr, nullptr);

    // --- layer 2 + fused layer 3 transforms ---
    gemm_tc2_kernel<64, true><<<gemmBlocks, 256, SMEM2>>>(bufA, N,
        w2h, w2l, b2, tx, tx + (long)N * 64, bufB);
    gather64_kernel<true><<<gatherBlocks, 256>>>(tx, bufB, N,
        W3, L3, b3, ev, out);

    // --- ev gather + global min, then mask ---
    gatherev_min_kernel<<<nodeBlocks, 256>>>(ev, out, N);
    mask_kernel<<<nodeBlocks, 256>>>(out, cs, ms, N);
}

// round 7
// speedup vs baseline: 1.7863x; 1.2803x over previous
#include <cuda_runtime.h>
#include <cuda_bf16.h>
#include <cstdint>

#define MAX_N 50000
#define MAX_E 800000
#define HDIM  64

// ---------------- scratch (no allocations allowed) ----------------
__device__ float g_tx[2L * MAX_N * HDIM];   // [2][N][64] per-relation transforms
__device__ float g_bufA[MAX_N * HDIM];
__device__ float g_bufB[MAX_N * HDIM];
__device__ float g_ev[2L * MAX_N * 2];      // [2][N][2] layer-3 messages
__device__ int   g_cnt[MAX_N];
__device__ int   g_off[MAX_N + 1];
__device__ int   g_pos[MAX_N];
__device__ int   g_bsum[64];                // block sums; -1 = not ready (sentinel)
__device__ unsigned g_elist[MAX_E];         // packed: src | (etype<<16)   (src < 65536)
__device__ unsigned g_min_key;
// pre-split bf16 weights: [3][K][64] hi/lo per layer
__device__ __nv_bfloat16 g_w1h[3 * 128 * 64], g_w1l[3 * 128 * 64];
__device__ __nv_bfloat16 g_w2h[3 * 64 * 64],  g_w2l[3 * 64 * 64];

// monotone float<->uint encoding so atomicMin(uint) == float min
__device__ __forceinline__ unsigned fenc(float f) {
    unsigned b = __float_as_uint(f);
    return (b & 0x80000000u) ? ~b : (b | 0x80000000u);
}
__device__ __forceinline__ float fdec(unsigned k) {
    unsigned b = (k & 0x80000000u) ? (k ^ 0x80000000u) : ~k;
    return __uint_as_float(b);
}
__device__ __forceinline__ void split_bf16(float v, __nv_bfloat16& h, __nv_bfloat16& l) {
    h = __float2bfloat16(v);
    l = __float2bfloat16(v - __bfloat162float(h));
}

// ================= setup: presplit weights + zero counters + sentinels =================
__global__ void setup_kernel(const float* __restrict__ W1, const float* __restrict__ L1,
                             const float* __restrict__ W2, const float* __restrict__ L2,
                             int N)
{
    int i = blockIdx.x * blockDim.x + threadIdx.x;
    if (i < 24576) {
        float v = (i < 16384) ? W1[i] : L1[i - 16384];
        split_bf16(v, g_w1h[i], g_w1l[i]);
    } else if (i < 36864) {
        int j = i - 24576;
        float v = (j < 8192) ? W2[j] : L2[j - 8192];
        split_bf16(v, g_w2h[j], g_w2l[j]);
    }
    if (i < N) g_cnt[i] = 0;
    if (i < 64) g_bsum[i] = -1;
    if (i == 0) g_min_key = 0xFFFFFFFFu;
}

// ================= CSR build =================
__global__ void hist_kernel(const int* __restrict__ dst, int E) {
    int e = blockIdx.x * blockDim.x + threadIdx.x;
    if (e < E) atomicAdd(&g_cnt[dst[e]], 1);
}

// single-kernel exclusive scan with parallel lookback (49 blocks, sentinel -1)
__global__ void __launch_bounds__(1024) scan_kernel(int N, int E) {
    __shared__ int sa[1024], sb[1024];
    __shared__ int bpre;
    const int tid = threadIdx.x;
    const int i = blockIdx.x * 1024 + tid;
    int v = (i < N) ? g_cnt[i] : 0;
    sa[tid] = v;
    __syncthreads();
    int* in = sa; int* out = sb;
    #pragma unroll
    for (int o = 1; o < 1024; o <<= 1) {
        out[tid] = in[tid] + (tid >= o ? in[tid - o] : 0);
        __syncthreads();
        int* t = in; in = out; out = t;
    }
    if (tid == 1023)
        ((volatile int*)g_bsum)[blockIdx.x] = in[1023];
    if (tid < 32) {
        int run = 0;
        for (int base = 0; base < blockIdx.x; base += 32) {
            int idx = base + tid;
            int bv = 0;
            if (idx < blockIdx.x) {
                do { bv = ((volatile int*)g_bsum)[idx]; } while (bv < 0);
            }
            #pragma unroll
            for (int o = 16; o; o >>= 1) bv += __shfl_xor_sync(0xffffffffu, bv, o);
            run += bv;
        }
        if (tid == 0) bpre = run;
    }
    __syncthreads();
    if (i < N) {
        int o = bpre + in[tid] - v;
        g_off[i] = o;
        g_pos[i] = o;
    }
    if (i == 0) g_off[N] = E;
}

__global__ void fill_kernel(const int* __restrict__ src,
                            const int* __restrict__ dst,
                            const int* __restrict__ et, int E) {
    int e = blockIdx.x * blockDim.x + threadIdx.x;
    if (e >= E) return;
    int p = atomicAdd(&g_pos[dst[e]], 1);
    g_elist[p] = (unsigned)src[e] | ((unsigned)et[e] << 16);
}

// ================= tensor-core helpers =================
__device__ __forceinline__ void ldsm_x4(uint32_t* r, const void* p) {
    uint32_t a = (uint32_t)__cvta_generic_to_shared(p);
    asm volatile("ldmatrix.sync.aligned.m8n8.x4.shared.b16 {%0,%1,%2,%3}, [%4];"
        : "=r"(r[0]), "=r"(r[1]), "=r"(r[2]), "=r"(r[3]) : "r"(a));
}
__device__ __forceinline__ void ldsm_x2t(uint32_t* r, const void* p) {
    uint32_t a = (uint32_t)__cvta_generic_to_shared(p);
    asm volatile("ldmatrix.sync.aligned.m8n8.x2.trans.shared.b16 {%0,%1}, [%2];"
        : "=r"(r[0]), "=r"(r[1]) : "r"(a));
}
__device__ __forceinline__ void mma_bf16(float* c, const uint32_t* a, const uint32_t* b) {
    asm volatile("mma.sync.aligned.m16n8k16.row.col.f32.bf16.bf16.f32 "
        "{%0,%1,%2,%3}, {%4,%5,%6,%7}, {%8,%9}, {%0,%1,%2,%3};"
        : "+f"(c[0]), "+f"(c[1]), "+f"(c[2]), "+f"(c[3])
        : "r"(a[0]), "r"(a[1]), "r"(a[2]), "r"(a[3]), "r"(b[0]), "r"(b[1]));
}

// ================= tensor-core triple GEMM v3 (BM=128, 512 threads) =================
// 16 warps: 4 in M (32 rows each), 4 in N (48 cols each of the 192 total).
template<int K, bool RELU_IN>
__global__ void __launch_bounds__(512, 1) gemm_tc2_kernel(
    const float* __restrict__ A, int M,
    const __nv_bfloat16* __restrict__ Wh, const __nv_bfloat16* __restrict__ Wl,
    const float* __restrict__ bias,
    float* __restrict__ C0, float* __restrict__ C1, float* __restrict__ Cl)
{
    constexpr int BM = 128;
    constexpr int AS = K + 8;
    constexpr int WS = 72;
    extern __shared__ __nv_bfloat16 sm[];
    __nv_bfloat16* Ahi = sm;
    __nv_bfloat16* Alo = Ahi + BM * AS;
    __nv_bfloat16* Whs = Alo + BM * AS;
    __nv_bfloat16* Wls = Whs + 3 * K * WS;

    const int tid  = threadIdx.x;
    const int lane = tid & 31;
    const int warp = tid >> 5;
    const int rowBase = blockIdx.x * BM;

    for (int u = tid; u < 3 * K * 8; u += 512) {
        int row = u >> 3, col = (u & 7) * 8;
        *(uint4*)&Whs[row * WS + col] = *(const uint4*)&Wh[row * 64 + col];
        *(uint4*)&Wls[row * WS + col] = *(const uint4*)&Wl[row * 64 + col];
    }
    for (int i = tid * 4; i < BM * K; i += 2048) {
        int r = i / K, kq = i % K;
        float4 v = make_float4(0.f, 0.f, 0.f, 0.f);
        if (rowBase + r < M) v = *(const float4*)&A[(long)(rowBase + r) * K + kq];
        float vv[4] = {v.x, v.y, v.z, v.w};
        #pragma unroll
        for (int j = 0; j < 4; j++) {
            float x = RELU_IN ? fmaxf(vv[j], 0.f) : vv[j];
            __nv_bfloat16 h, l;
            split_bf16(x, h, l);
            Ahi[r * AS + kq + j] = h;
            Alo[r * AS + kq + j] = l;
        }
    }
    __syncthreads();

    const int mw = (warp & 3) * 32;
    const int nw = (warp >> 2) * 48;
    const int lr = lane & 15;
    const int aCol = (lane >> 4) * 8;

    float acc[2][6][4];
    #pragma unroll
    for (int mt = 0; mt < 2; mt++)
        #pragma unroll
        for (int j = 0; j < 6; j++)
            #pragma unroll
            for (int q = 0; q < 4; q++) acc[mt][j][q] = 0.f;

    #pragma unroll
    for (int kk = 0; kk < K / 16; kk++) {
        uint32_t ah[2][4], al[2][4];
        #pragma unroll
        for (int mt = 0; mt < 2; mt++) {
            ldsm_x4(ah[mt], &Ahi[(mw + mt * 16 + lr) * AS + kk * 16 + aCol]);
            ldsm_x4(al[mt], &Alo[(mw + mt * 16 + lr) * AS + kk * 16 + aCol]);
        }
        #pragma unroll
        for (int j = 0; j < 6; j++) {
            int n = nw + j * 8;
            int w = n >> 6, nc = n & 63;
            long woff = (long)(w * K + kk * 16 + lr) * WS + nc;
            uint32_t bh[2], bl[2];
            ldsm_x2t(bh, &Whs[woff]);
            ldsm_x2t(bl, &Wls[woff]);
            mma_bf16(acc[0][j], ah[0], bh);
            mma_bf16(acc[0][j], ah[0], bl);
            mma_bf16(acc[0][j], al[0], bh);
            mma_bf16(acc[1][j], ah[1], bh);
            mma_bf16(acc[1][j], ah[1], bl);
            mma_bf16(acc[1][j], al[1], bh);
        }
    }

    float* Cs[3] = {C0, C1, Cl};
    #pragma unroll
    for (int mt = 0; mt < 2; mt++) {
        const int r0 = rowBase + mw + mt * 16 + (lane >> 2);
        #pragma unroll
        for (int j = 0; j < 6; j++) {
            int n = nw + j * 8;
            int w = n >> 6;
            int nc = (n & 63) + 2 * (lane & 3);
            float b0 = 0.f, b1 = 0.f;
            if (w == 2) { b0 = bias[nc]; b1 = bias[nc + 1]; }
            if (r0 < M)
                *(float2*)&Cs[w][(long)r0 * 64 + nc] =
                    make_float2(acc[mt][j][0] + b0, acc[mt][j][1] + b1);
            if (r0 + 8 < M)
                *(float2*)&Cs[w][(long)(r0 + 8) * 64 + nc] =
                    make_float2(acc[mt][j][2] + b0, acc[mt][j][3] + b1);
        }
    }
}

// ================= gather64: one warp per node, MLP=4 =================
template<bool FINAL>
__global__ void gather64_kernel(const float* __restrict__ t,
                                float* __restrict__ agg, int N,
                                const float* __restrict__ W3,
                                const float* __restrict__ L3,
                                const float* __restrict__ b3,
                                float* __restrict__ ev,
                                float* __restrict__ out)
{
    __shared__ float sW0[128], sW1[128], sL[128], sb[2];
    if (FINAL) {
        int tid = threadIdx.x;
        for (int i = tid; i < 128; i += blockDim.x) {
            sW0[i] = W3[i];
            sW1[i] = W3[128 + i];
            sL[i]  = L3[i];
        }
        if (tid < 2) sb[tid] = b3[tid];
        __syncthreads();
    }

    int w = (int)((blockIdx.x * (long)blockDim.x + threadIdx.x) >> 5);
    int lane = threadIdx.x & 31;
    if (w >= N) return;
    int beg = g_off[w], end = g_off[w + 1];
    long o = (long)w * 64 + lane * 2;
    float2 a0 = *(float2*)&agg[o];
    float2 a1 = make_float2(0.f, 0.f), a2 = a1, a3 = a1;
    int e = beg;
    for (; e + 4 <= end; e += 4) {
        unsigned p0 = g_elist[e],     p1 = g_elist[e + 1];
        unsigned p2 = g_elist[e + 2], p3 = g_elist[e + 3];
        float2 v0 = *(const float2*)&t[(long)((p0 >> 16) * N + (p0 & 0xFFFFu)) * 64 + lane * 2];
        float2 v1 = *(const float2*)&t[(long)((p1 >> 16) * N + (p1 & 0xFFFFu)) * 64 + lane * 2];
        float2 v2 = *(const float2*)&t[(long)((p2 >> 16) * N + (p2 & 0xFFFFu)) * 64 + lane * 2];
        float2 v3 = *(const float2*)&t[(long)((p3 >> 16) * N + (p3 & 0xFFFFu)) * 64 + lane * 2];
        a0.x += v0.x; a0.y += v0.y;
        a1.x += v1.x; a1.y += v1.y;
        a2.x += v2.x; a2.y += v2.y;
        a3.x += v3.x; a3.y += v3.y;
    }
    for (; e < end; e++) {
        unsigned p = g_elist[e];
        float2 v = *(const float2*)&t[(long)((p >> 16) * N + (p & 0xFFFFu)) * 64 + lane * 2];
        a0.x += v.x; a0.y += v.y;
    }
    a0.x += a1.x + a2.x + a3.x;
    a0.y += a1.y + a2.y + a3.y;

    if (!FINAL) {
        *(float2*)&agg[o] = a0;
        return;
    }

    float x0 = fmaxf(a0.x, 0.f), x1 = fmaxf(a0.y, 0.f);
    int k0 = lane * 2, k1 = lane * 2 + 1;
    float p0 = x0 * sW0[k0 * 2 + 0] + x1 * sW0[k1 * 2 + 0];
    float p1 = x0 * sW0[k0 * 2 + 1] + x1 * sW0[k1 * 2 + 1];
    float p2 = x0 * sW1[k0 * 2 + 0] + x1 * sW1[k1 * 2 + 0];
    float p3 = x0 * sW1[k0 * 2 + 1] + x1 * sW1[k1 * 2 + 1];
    float p4 = x0 * sL[k0 * 2 + 0]  + x1 * sL[k1 * 2 + 0];
    float p5 = x0 * sL[k0 * 2 + 1]  + x1 * sL[k1 * 2 + 1];
    #pragma unroll
    for (int off = 16; off; off >>= 1) {
        p0 += __shfl_xor_sync(0xffffffffu, p0, off);
        p1 += __shfl_xor_sync(0xffffffffu, p1, off);
        p2 += __shfl_xor_sync(0xffffffffu, p2, off);
        p3 += __shfl_xor_sync(0xffffffffu, p3, off);
        p4 += __shfl_xor_sync(0xffffffffu, p4, off);
        p5 += __shfl_xor_sync(0xffffffffu, p5, off);
    }
    if (lane == 0) {
        *(float2*)&ev[(long)w * 2]       = make_float2(p0, p1);
        *(float2*)&ev[((long)N + w) * 2] = make_float2(p2, p3);
        *(float2*)&out[(long)w * 2]      = make_float2(p4 + sb[0], p5 + sb[1]);
    }
}

// ================= ev-gather + global min (fused) =================
__global__ void gatherev_min_kernel(const float* __restrict__ ev,
                                    float* __restrict__ out, int N)
{
    int n = blockIdx.x * blockDim.x + threadIdx.x;
    float m = 3.402823466e+38f;
    if (n < N) {
        int beg = g_off[n], end = g_off[n + 1];
        float2 a0 = *(float2*)&out[n * 2];
        float2 a1 = make_float2(0.f, 0.f), a2 = a1, a3 = a1;
        int e = beg;
        for (; e + 4 <= end; e += 4) {
            unsigned p0 = g_elist[e],     p1 = g_elist[e + 1];
            unsigned p2 = g_elist[e + 2], p3 = g_elist[e + 3];
            float2 v0 = *(const float2*)&ev[(long)((p0 >> 16) * N + (p0 & 0xFFFFu)) * 2];
            float2 v1 = *(const float2*)&ev[(long)((p1 >> 16) * N + (p1 & 0xFFFFu)) * 2];
            float2 v2 = *(const float2*)&ev[(long)((p2 >> 16) * N + (p2 & 0xFFFFu)) * 2];
            float2 v3 = *(const float2*)&ev[(long)((p3 >> 16) * N + (p3 & 0xFFFFu)) * 2];
            a0.x += v0.x; a0.y += v0.y;
            a1.x += v1.x; a1.y += v1.y;
            a2.x += v2.x; a2.y += v2.y;
            a3.x += v3.x; a3.y += v3.y;
        }
        for (; e < end; e++) {
            unsigned p = g_elist[e];
            float2 v = *(const float2*)&ev[(long)((p >> 16) * N + (p & 0xFFFFu)) * 2];
            a0.x += v.x; a0.y += v.y;
        }
        a0.x += a1.x + a2.x + a3.x;
        a0.y += a1.y + a2.y + a3.y;
        *(float2*)&out[n * 2] = a0;
        m = fminf(a0.x, a0.y);
    }
    #pragma unroll
    for (int o = 16; o; o >>= 1)
        m = fminf(m, __shfl_xor_sync(0xffffffffu, m, o));
    __shared__ float sm[8];
    if ((threadIdx.x & 31) == 0) sm[threadIdx.x >> 5] = m;
    __syncthreads();
    if (threadIdx.x < 8) {
        m = sm[threadIdx.x];
        #pragma unroll
        for (int o = 4; o; o >>= 1)
            m = fminf(m, __shfl_xor_sync(0xffu, m, o));
        if (threadIdx.x == 0) atomicMin(&g_min_key, fenc(m));
    }
}

__global__ void mask_kernel(float* __restrict__ out,
                            const int* __restrict__ cs,
                            const int* __restrict__ ms, int N)
{
    int n = blockIdx.x * blockDim.x + threadIdx.x;
    if (n >= N) return;
    float mn = fdec(g_min_key) - 1.0f;
    float2 v = *(float2*)&out[n * 2];
    if (cs[n] >= ms[n] - 1) v.x = mn;
    if (cs[n] == 0)         v.y = mn;
    *(float2*)&out[n * 2] = v;
}

// ================= launch =================
extern "C" void kernel_launch(void* const* d_in, const int* in_sizes, int n_in,
                              void* d_out, int out_size)
{
    const float* x  = (const float*)d_in[0];
    const int* src  = (const int*)d_in[1];
    const int* dst  = (const int*)d_in[2];
    const int* et   = (const int*)d_in[3];
    const int* cs   = (const int*)d_in[4];
    const int* ms   = (const int*)d_in[5];
    const float* W1 = (const float*)d_in[6];
    const float* L1 = (const float*)d_in[7];
    const float* b1 = (const float*)d_in[8];
    const float* W2 = (const float*)d_in[9];
    const float* L2 = (const float*)d_in[10];
    const float* b2 = (const float*)d_in[11];
    const float* W3 = (const float*)d_in[12];
    const float* L3 = (const float*)d_in[13];
    const float* b3 = (const float*)d_in[14];

    const int N = in_sizes[0] / 128;
    const int E = in_sizes[1];
    float* out = (float*)d_out;

    float *tx, *bufA, *bufB, *ev;
    __nv_bfloat16 *w1h, *w1l, *w2h, *w2l;
    cudaGetSymbolAddress((void**)&tx,   g_tx);
    cudaGetSymbolAddress((void**)&bufA, g_bufA);
    cudaGetSymbolAddress((void**)&bufB, g_bufB);
    cudaGetSymbolAddress((void**)&ev,   g_ev);
    cudaGetSymbolAddress((void**)&w1h,  g_w1h);
    cudaGetSymbolAddress((void**)&w1l,  g_w1l);
    cudaGetSymbolAddress((void**)&w2h,  g_w2h);
    cudaGetSymbolAddress((void**)&w2l,  g_w2l);

    constexpr int SMEM1 = (2 * 128 * (128 + 8) + 2 * 3 * 128 * 72) * 2;  // 180224
    constexpr int SMEM2 = (2 * 128 * (64 + 8)  + 2 * 3 * 64  * 72) * 2;  // 92160
    cudaFuncSetAttribute(gemm_tc2_kernel<128, false>,
                         cudaFuncAttributeMaxDynamicSharedMemorySize, SMEM1);
    cudaFuncSetAttribute(gemm_tc2_kernel<64, true>,
                         cudaFuncAttributeMaxDynamicSharedMemorySize, SMEM2);

    // side stream + events for overlapping the CSR build with layer-1 GEMM.
    // Created once (host-side objects only; per-call work is unchanged).
    static cudaStream_t s2 = nullptr;
    static cudaEvent_t evFork = nullptr, evCSR = nullptr;
    if (!s2) {
        cudaStreamCreateWithFlags(&s2, cudaStreamNonBlocking);
        cudaEventCreateWithFlags(&evFork, cudaEventDisableTiming);
        cudaEventCreateWithFlags(&evCSR,  cudaEventDisableTiming);
    }

    int gemmBlocks = (N + 127) / 128;
    int nodeBlocks = (N + 255) / 256;
    int edgeBlocks = (E + 255) / 256;
    int gatherBlocks = (N * 32 + 255) / 256;
    int scanBlocks = (N + 1023) / 1024;

    // --- setup feeds both branches ---
    setup_kernel<<<nodeBlocks, 256>>>(W1, L1, W2, L2, N);
    cudaEventRecord(evFork, 0);

    // --- branch A (side stream): CSR build ---
    cudaStreamWaitEvent(s2, evFork, 0);
    hist_kernel<<<edgeBlocks, 256, 0, s2>>>(dst, E);
    scan_kernel<<<scanBlocks, 1024, 0, s2>>>(N, E);
    fill_kernel<<<edgeBlocks, 256, 0, s2>>>(src, dst, et, E);
    cudaEventRecord(evCSR, s2);

    // --- branch B (main stream): layer-1 GEMM (independent of CSR) ---
    gemm_tc2_kernel<128, false><<<gemmBlocks, 512, SMEM1>>>(x, N,
        w1h, w1l, b1, tx, tx + (long)N * 64, bufA);

    // --- join: gather needs CSR + tx ---
    cudaStreamWaitEvent(0, evCSR, 0);
    gather64_kernel<false><<<gatherBlocks, 256>>>(tx, bufA, N,
        nullptr, nullptr, nullptr, nullptr, nullptr);

    // --- layer 2 + fused layer 3 transforms ---
    gemm_tc2_kernel<64, true><<<gemmBlocks, 512, SMEM2>>>(bufA, N,
        w2h, w2l, b2, tx, tx + (long)N * 64, bufB);
    gather64_kernel<true><<<gatherBlocks, 256>>>(tx, bufB, N,
        W3, L3, b3, ev, out);

    // --- ev gather + global min, then mask ---
    gatherev_min_kernel<<<nodeBlocks, 256>>>(ev, out, N);
    mask_kernel<<<nodeBlocks, 256>>>(out, cs, ms, N);
}